// round 13
// baseline (speedup 1.0000x reference)
#include <cuda_runtime.h>
#include <cuda_bf16.h>
#include <cuda_fp16.h>
#include <cstdint>

// ---------------- problem constants ----------------
#define DIN   4096
#define DOUT  4096
#define MROWS 8192          // B*S = 4*2048
#define R0    32
#define R1    8
#define RTOT  40
#define NEXP  3
#define SCALING 0.5f        // 16/32

// ---------------- device scratch ----------------
__device__ __align__(256) float  g_sumw[DOUT * RTOT];   // masked coef sums  [O, 40]
__device__ __align__(256) float  g_fw  [DOUT * RTOT];   // fourier-transformed [O, 40]
__device__ __align__(256) __half g_wh[(size_t)DOUT * DIN];   // W_eff fp16
__device__ __align__(256) __half g_xh[(size_t)MROWS * DIN];  // x fp16
__device__ unsigned int g_viol[2];   // [0]: "not int32-like", [1]: "not float32-like"

// ---------------- helpers ----------------
__device__ __forceinline__ uint32_t smem_u32(const void* p) {
    uint32_t a;
    asm("{ .reg .u64 t; cvta.to.shared.u64 t, %1; cvt.u32.u64 %0, t; }" : "=r"(a) : "l"(p));
    return a;
}
#define SMEM_SWIZZLE_128B(off) ((off) ^ (((off) >> 3) & 0x70))

__device__ __forceinline__ void cp_async16(uint32_t saddr, const void* gaddr) {
    asm volatile("cp.async.cg.shared.global [%0], [%1], 16;" :: "r"(saddr), "l"(gaddr));
}
__device__ __forceinline__ void cp_commit() {
    asm volatile("cp.async.commit_group;" ::: "memory");
}
template <int N>
__device__ __forceinline__ void cp_wait() {
    asm volatile("cp.async.wait_group %0;" :: "n"(N) : "memory");
}

__device__ __forceinline__ void ldm_x4(uint32_t& r0, uint32_t& r1, uint32_t& r2, uint32_t& r3,
                                       uint32_t addr) {
    asm volatile("ldmatrix.sync.aligned.m8n8.x4.shared.b16 {%0,%1,%2,%3}, [%4];"
                 : "=r"(r0), "=r"(r1), "=r"(r2), "=r"(r3) : "r"(addr));
}

__device__ __forceinline__ void mma_f16(float& c0, float& c1, float& c2, float& c3,
                                        uint32_t a0, uint32_t a1, uint32_t a2, uint32_t a3,
                                        uint32_t b0, uint32_t b1) {
    asm volatile(
        "mma.sync.aligned.m16n8k16.row.col.f32.f16.f16.f32 "
        "{%0,%1,%2,%3}, {%4,%5,%6,%7}, {%8,%9}, {%0,%1,%2,%3};"
        : "+f"(c0), "+f"(c1), "+f"(c2), "+f"(c3)
        : "r"(a0), "r"(a1), "r"(a2), "r"(a3), "r"(b0), "r"(b1));
}

// ============================================================================
// Kernel 0a/0b: mask dtype detection (uint8 / int32 / float32 bools).
// ============================================================================
__global__ void k_viol_init() { g_viol[0] = 0u; g_viol[1] = 0u; }

__global__ void k_detect(const unsigned int* __restrict__ w) {
    unsigned int v = w[blockIdx.x * blockDim.x + threadIdx.x];
    if (v > 1u) atomicOr(&g_viol[0], 1u);
    if (v != 0u && v != 0x3f800000u) atomicOr(&g_viol[1], 1u);
}

// ============================================================================
// Kernel 1: masked coefficient sum over experts.  g_sumw[o, r]
// ============================================================================
__device__ __forceinline__ bool mask_at(const void* m, int j, int mode) {
    if (mode == 1) return ((const int*)m)[j] != 0;
    if (mode == 2) return ((const float*)m)[j] != 0.f;
    return ((const unsigned char*)m)[j] != 0;
}

__global__ void k_sum_coefs(const float* __restrict__ c0, const float* __restrict__ c1,
                            const void* __restrict__ m0, const void* __restrict__ m1) {
    int idx = blockIdx.x * blockDim.x + threadIdx.x;
    if (idx >= DOUT * RTOT) return;
    const int mode = (g_viol[0] == 0u) ? 1 : ((g_viol[1] == 0u) ? 2 : 0);
    int o = idx / RTOT, r = idx % RTOT;
    float s = 0.f;
    if (r < R0) {
        #pragma unroll
        for (int e = 0; e < NEXP; ++e) {
            int j = e * DOUT * R0 + o * R0 + r;
            s += mask_at(m0, j, mode) ? c0[j] : 0.f;
        }
    } else {
        int rr = r - R0;
        #pragma unroll
        for (int e = 0; e < NEXP; ++e) {
            int j = e * DOUT * R1 + o * R1 + rr;
            s += mask_at(m1, j, mode) ? c1[j] : 0.f;
        }
    }
    g_sumw[o * RTOT + r] = s;
}

// ============================================================================
// Kernel 2a: init g_fw with DC + Nyquist terms.
// ============================================================================
__global__ void k_fw_init() {
    int idx = blockIdx.x * blockDim.x + threadIdx.x;   // over 4096*40
    if (idx >= DOUT * RTOT) return;
    int t = idx / RTOT, r = idx % RTOT;
    const float inv = 0.015625f;                       // 1/sqrt(4096)
    float sgn = (t & 1) ? -inv : inv;
    g_fw[idx] = g_sumw[r] * inv + g_sumw[(DOUT - 1) * RTOT + r] * sgn;
}

// ============================================================================
// Kernel 2b: frequency-parallel Fourier accumulation with rotation recurrence.
// grid (32, 16): blockIdx.x = t-tile of 128, blockIdx.y = 128-freq chunk.
// ============================================================================
__global__ void k_transform() {
    __shared__ float sc[128 * RTOT];       // 64 freqs (cos,sin rows) at a time
    int t = blockIdx.x * 128 + threadIdx.x;
    float acc[RTOT];
    #pragma unroll
    for (int r = 0; r < RTOT; ++r) acc[r] = 0.f;

    const float TWO_PI_OVER_N = 0.00153398078788564123f;
    float cd, sd;
    {
        int kt = t & 4095;
        int kt2 = (kt <= 2048) ? kt : (kt - 4096);
        __sincosf((float)kt2 * TWO_PI_OVER_N, &sd, &cd);
    }

    #pragma unroll
    for (int half = 0; half < 2; ++half) {
        int fs = 1 + blockIdx.y * 128 + half * 64;
        int nf = 2048 - fs; if (nf > 64) nf = 64;      // f max = 2047
        if (nf <= 0) break;
        int row0 = 2 * fs - 1;
        __syncthreads();
        for (int i = threadIdx.x; i < 2 * nf; i += 128) {
            const float4* src = (const float4*)(g_sumw + (size_t)(row0 + i) * RTOT);
            float4* dst = (float4*)(sc + i * RTOT);
            #pragma unroll
            for (int q = 0; q < 10; ++q) dst[q] = src[q];
        }
        __syncthreads();

        float cv, sv;
        {
            int k = (fs * t) & 4095;
            int k2 = (k <= 2048) ? k : (k - 4096);
            __sincosf((float)k2 * TWO_PI_OVER_N, &sv, &cv);
        }

        for (int j = 0; j < nf; ++j) {
            const float4* cc = (const float4*)(sc + (2 * j) * RTOT);
            const float4* ss = (const float4*)(sc + (2 * j + 1) * RTOT);
            #pragma unroll
            for (int q = 0; q < 10; ++q) {
                float4 a = cc[q]; float4 b = ss[q];
                acc[4*q+0] += a.x * cv + b.x * sv;
                acc[4*q+1] += a.y * cv + b.y * sv;
                acc[4*q+2] += a.z * cv + b.z * sv;
                acc[4*q+3] += a.w * cv + b.w * sv;
            }
            float ncv = cv * cd - sv * sd;
            sv = sv * cd + cv * sd;
            cv = ncv;
        }
    }
    const float s2 = 0.02209708691207961102f;          // sqrt(2/4096)
    float* dst = g_fw + (size_t)t * RTOT;
    #pragma unroll
    for (int r = 0; r < RTOT; ++r) atomicAdd(dst + r, acc[r] * s2);
}

// ============================================================================
// Kernel 3: W_eff = W_base + 0.5*(FW@enc); store fp16.
// ============================================================================
__global__ void k_build_w(const float* __restrict__ Wb,
                          const float* __restrict__ enc0,
                          const float* __restrict__ enc1) {
    __shared__ float fws[64 * RTOT];
    int d  = blockIdx.x * 128 + threadIdx.x;
    int o0 = blockIdx.y * 64;
    for (int i = threadIdx.x; i < 64 * RTOT / 4; i += 128)
        ((float4*)fws)[i] = ((const float4*)(g_fw + (size_t)o0 * RTOT))[i];
    float e[RTOT];
    #pragma unroll
    for (int r = 0; r < R0; ++r) e[r] = enc0[(size_t)r * DIN + d];
    #pragma unroll
    for (int r = 0; r < R1; ++r) e[R0 + r] = enc1[(size_t)r * DIN + d];
    __syncthreads();
    for (int oo = 0; oo < 64; ++oo) {
        size_t o = (size_t)(o0 + oo);
        float s = 0.f;
        const float4* fr = (const float4*)(fws + oo * RTOT);
        #pragma unroll
        for (int q = 0; q < 10; ++q) {
            float4 fv = fr[q];
            s += fv.x * e[4*q] + fv.y * e[4*q+1] + fv.z * e[4*q+2] + fv.w * e[4*q+3];
        }
        float v = Wb[o * DIN + d] + SCALING * s;
        g_wh[o * DIN + d] = __float2half_rn(v);
    }
}

// ============================================================================
// Kernel 4: convert x to fp16.  (runs on a SIDE STREAM, overlapped with the
// W-path chain above — x path and W path are independent until the GEMM.)
// ============================================================================
__global__ void k_cvt_x(const float* __restrict__ x) {
    size_t idx = (size_t)blockIdx.x * blockDim.x + threadIdx.x;  // over MROWS*DIN/4
    float4 v = ((const float4*)x)[idx];
    __half2 h01 = __floats2half2_rn(v.x, v.y);
    __half2 h23 = __floats2half2_rn(v.z, v.w);
    ((__half2*)g_xh)[2*idx]   = h01;
    ((__half2*)g_xh)[2*idx+1] = h23;
}

// ============================================================================
// Kernel 5: GEMM (R12 config — best: 128x128 CTA tile, 8 warps 64x32, 3-stage
// ring, one barrier per iter, spread cp.async issue, 2 CTAs/SM). UNCHANGED.
// ============================================================================
#define BM 128
#define BN 128
#define BK 64
#define STAGE_BYTES 32768   // A 16KB + B 16KB
#define NSTAGE 3
#define GEMM_SMEM   (STAGE_BYTES * NSTAGE)   // 98304
#define ITERS 64            // 4096 / 64

__global__ __launch_bounds__(256, 2) void k_gemm(const float* __restrict__ bias,
                                                 float* __restrict__ out) {
    extern __shared__ __align__(1024) unsigned char dynsmem[];
    const uint32_t smem_base = smem_u32(dynsmem);

    const int tid = threadIdx.x;
    const int wid = tid >> 5;
    const int lane = tid & 31;
    const int wm = wid & 1;          // 2 warps along M
    const int wn = wid >> 1;         // 4 warps along N
    const int m0 = blockIdx.y * BM;  // gridDim.y = 64
    const int n0 = blockIdx.x * BN;  // gridDim.x = 32

    const int ld_row = tid >> 3;          // 0..31 (+32*i)
    const int ld_c   = tid & 7;           // 16B column within 128B row

    float acc[4][4][4];                   // [mi][ni][reg]
    #pragma unroll
    for (int mi = 0; mi < 4; ++mi)
        #pragma unroll
        for (int ni = 0; ni < 4; ++ni)
            #pragma unroll
            for (int j = 0; j < 4; ++j) acc[mi][ni][j] = 0.f;

    const int a_row_l = (lane & 15);
    const int a_col_l = (lane & 16) ? 16 : 0;
    const int b_row_l = (lane & 7) + ((lane & 16) ? 8 : 0);
    const int b_col_l = (lane & 8) ? 16 : 0;

    const __half* Ap0 = g_xh + (size_t)m0 * DIN;
    const __half* Bp0 = g_wh + (size_t)n0 * DIN;

    auto issue_part = [&](int it, int slot, int part) {
        const int kc = it << 6;
        const int row = ld_row + part * 32;
        const uint32_t off = SMEM_SWIZZLE_128B((uint32_t)(row * 128 + ld_c * 16));
        const uint32_t sAb = smem_base + (uint32_t)slot * STAGE_BYTES;
        cp_async16(sAb + off,         Ap0 + kc + (size_t)row * DIN + ld_c * 8);
        cp_async16(sAb + 16384 + off, Bp0 + kc + (size_t)row * DIN + ld_c * 8);
    };
    auto issue_full = [&](int it, int slot) {
        #pragma unroll
        for (int p = 0; p < 4; ++p) issue_part(it, slot, p);
        cp_commit();
    };

    issue_full(0, 0);
    issue_full(1, 1);

    int slot = 0;        // slot of iter 'it'
    for (int it = 0; it < ITERS; ++it) {
        if (it + 1 < ITERS) cp_wait<1>();   // oldest (stage it) complete
        else                cp_wait<0>();
        __syncthreads();                    // compute(it-1) done; its slot is free

        const bool do_issue = (it + 2 < ITERS);
        int ns = slot + 2; if (ns >= NSTAGE) ns -= NSTAGE;

        const uint32_t sAb = smem_base + (uint32_t)slot * STAGE_BYTES;
        const uint32_t sBb = sAb + 16384;

        #pragma unroll
        for (int ks = 0; ks < 4; ++ks) {
            if (do_issue) issue_part(it + 2, ns, ks);   // spread STS across ks
            uint32_t a[4][4];
            uint32_t b[2][4];
            #pragma unroll
            for (int mi = 0; mi < 4; ++mi) {
                const int row = wm * 64 + mi * 16 + a_row_l;
                const int col = ks * 32 + a_col_l;
                const uint32_t addr = sAb + SMEM_SWIZZLE_128B((uint32_t)(row * 128 + col));
                ldm_x4(a[mi][0], a[mi][1], a[mi][2], a[mi][3], addr);
            }
            #pragma unroll
            for (int np = 0; np < 2; ++np) {
                const int row = wn * 32 + np * 16 + b_row_l;
                const int col = ks * 32 + b_col_l;
                const uint32_t addr = sBb + SMEM_SWIZZLE_128B((uint32_t)(row * 128 + col));
                ldm_x4(b[np][0], b[np][1], b[np][2], b[np][3], addr);
            }
            #pragma unroll
            for (int mi = 0; mi < 4; ++mi)
                #pragma unroll
                for (int ni = 0; ni < 4; ++ni) {
                    const uint32_t b0 = b[ni >> 1][(ni & 1) * 2];
                    const uint32_t b1 = b[ni >> 1][(ni & 1) * 2 + 1];
                    mma_f16(acc[mi][ni][0], acc[mi][ni][1], acc[mi][ni][2], acc[mi][ni][3],
                            a[mi][0], a[mi][1], a[mi][2], a[mi][3], b0, b1);
                }
        }
        if (do_issue) cp_commit();
        if (++slot >= NSTAGE) slot = 0;
    }

    // Epilogue: direct stores, float2 per fragment row, +bias.
    #pragma unroll
    for (int ni = 0; ni < 4; ++ni) {
        const int n = n0 + wn * 32 + ni * 8 + (lane & 3) * 2;
        const float bv0 = bias[n];
        const float bv1 = bias[n + 1];
        #pragma unroll
        for (int mi = 0; mi < 4; ++mi) {
            const int m = m0 + wm * 64 + mi * 16 + (lane >> 2);
            float2 v0 = make_float2(acc[mi][ni][0] + bv0, acc[mi][ni][1] + bv1);
            float2 v1 = make_float2(acc[mi][ni][2] + bv0, acc[mi][ni][3] + bv1);
            *(float2*)(out + (size_t)m * DOUT + n)       = v0;
            *(float2*)(out + (size_t)(m + 8) * DOUT + n) = v1;
        }
    }
}

// ============================================================================
// launch — fork/join: x-conversion on a side stream, overlapped with the
// W-path prep chain. Streams/events created ONCE at first (uncaptured) call;
// during graph capture only capturable ops are issued (launch/record/wait).
// ============================================================================
extern "C" void kernel_launch(void* const* d_in, const int* in_sizes, int n_in,
                              void* d_out, int out_size) {
    const float* x      = (const float*)d_in[0];
    const float* W_base = (const float*)d_in[1];
    const float* b_base = (const float*)d_in[2];
    const float* enc0   = (const float*)d_in[3];
    const float* enc1   = (const float*)d_in[4];
    const float* coefs0 = (const float*)d_in[5];
    const float* coefs1 = (const float*)d_in[6];
    const void*  mask0  = d_in[7];
    const void*  mask1  = d_in[8];
    float* out = (float*)d_out;

    static cudaStream_t s_side = nullptr;
    static cudaEvent_t  e_fork = nullptr, e_join = nullptr;
    if (s_side == nullptr) {
        cudaFuncSetAttribute(k_gemm, cudaFuncAttributeMaxDynamicSharedMemorySize, GEMM_SMEM);
        cudaStreamCreateWithFlags(&s_side, cudaStreamNonBlocking);
        cudaEventCreateWithFlags(&e_fork, cudaEventDisableTiming);
        cudaEventCreateWithFlags(&e_join, cudaEventDisableTiming);
    }

    // ---- fork: x path on side stream (independent of W path) ----
    cudaEventRecord(e_fork, 0);
    cudaStreamWaitEvent(s_side, e_fork, 0);
    k_cvt_x<<<(MROWS * DIN / 4) / 256, 256, 0, s_side>>>(x);
    cudaEventRecord(e_join, s_side);

    // ---- W path on the main (capture) stream ----
    k_viol_init<<<1, 1>>>();
    k_detect<<<(NEXP * DOUT * R0 / 4) / 256, 256>>>((const unsigned int*)mask0);
    k_sum_coefs<<<(DOUT * RTOT + 255) / 256, 256>>>(coefs0, coefs1, mask0, mask1);
    k_fw_init<<<(DOUT * RTOT + 255) / 256, 256>>>();
    k_transform<<<dim3(32, 16), 128>>>();
    k_build_w<<<dim3(32, 64), 128>>>(W_base, enc0, enc1);

    // ---- join: GEMM needs both g_xh and g_wh ----
    cudaStreamWaitEvent(0, e_join, 0);
    k_gemm<<<dim3(32, 64), 256, GEMM_SMEM>>>(b_base, out);
}

// round 14
// speedup vs baseline: 1.0085x; 1.0085x over previous
#include <cuda_runtime.h>
#include <cuda_bf16.h>
#include <cuda_fp16.h>
#include <cstdint>

// ---------------- problem constants ----------------
#define DIN   4096
#define DOUT  4096
#define MROWS 8192          // B*S = 4*2048
#define R0    32
#define R1    8
#define RTOT  40
#define NEXP  3
#define SCALING 0.5f        // 16/32

// ---------------- device scratch ----------------
__device__ __align__(256) float  g_sumw[DOUT * RTOT];   // masked coef sums  [O, 40]
__device__ __align__(256) float  g_fw  [DOUT * RTOT];   // fourier-transformed [O, 40]
__device__ __align__(256) __half g_wh[(size_t)DOUT * DIN];   // W_eff fp16
__device__ __align__(256) __half g_xh[(size_t)MROWS * DIN];  // x fp16
// statically zero-initialized; k_detect only ORs input-derived bits, so the
// value is idempotent across graph replays (deterministic).
__device__ unsigned int g_viol[2] = {0u, 0u};

// ---------------- helpers ----------------
__device__ __forceinline__ uint32_t smem_u32(const void* p) {
    uint32_t a;
    asm("{ .reg .u64 t; cvta.to.shared.u64 t, %1; cvt.u32.u64 %0, t; }" : "=r"(a) : "l"(p));
    return a;
}
#define SMEM_SWIZZLE_128B(off) ((off) ^ (((off) >> 3) & 0x70))

__device__ __forceinline__ void cp_async16(uint32_t saddr, const void* gaddr) {
    asm volatile("cp.async.cg.shared.global [%0], [%1], 16;" :: "r"(saddr), "l"(gaddr));
}
__device__ __forceinline__ void cp_commit() {
    asm volatile("cp.async.commit_group;" ::: "memory");
}
template <int N>
__device__ __forceinline__ void cp_wait() {
    asm volatile("cp.async.wait_group %0;" :: "n"(N) : "memory");
}

__device__ __forceinline__ void ldm_x4(uint32_t& r0, uint32_t& r1, uint32_t& r2, uint32_t& r3,
                                       uint32_t addr) {
    asm volatile("ldmatrix.sync.aligned.m8n8.x4.shared.b16 {%0,%1,%2,%3}, [%4];"
                 : "=r"(r0), "=r"(r1), "=r"(r2), "=r"(r3) : "r"(addr));
}

__device__ __forceinline__ void mma_f16(float& c0, float& c1, float& c2, float& c3,
                                        uint32_t a0, uint32_t a1, uint32_t a2, uint32_t a3,
                                        uint32_t b0, uint32_t b1) {
    asm volatile(
        "mma.sync.aligned.m16n8k16.row.col.f32.f16.f16.f32 "
        "{%0,%1,%2,%3}, {%4,%5,%6,%7}, {%8,%9}, {%0,%1,%2,%3};"
        : "+f"(c0), "+f"(c1), "+f"(c2), "+f"(c3)
        : "r"(a0), "r"(a1), "r"(a2), "r"(a3), "r"(b0), "r"(b1));
}

// ============================================================================
// Kernel 0: mask dtype detection (uint8 / int32 / float32 bools).
// ============================================================================
__global__ void k_detect(const unsigned int* __restrict__ w) {
    unsigned int v = w[blockIdx.x * blockDim.x + threadIdx.x];
    if (v > 1u) atomicOr(&g_viol[0], 1u);
    if (v != 0u && v != 0x3f800000u) atomicOr(&g_viol[1], 1u);
}

__device__ __forceinline__ bool mask_at(const void* m, int j, int mode) {
    if (mode == 1) return ((const int*)m)[j] != 0;
    if (mode == 2) return ((const float*)m)[j] != 0.f;
    return ((const unsigned char*)m)[j] != 0;
}

__device__ __forceinline__ float masked_sum(const float* c, const void* m,
                                            int o, int rr, int R, int mode) {
    float s = 0.f;
    #pragma unroll
    for (int e = 0; e < NEXP; ++e) {
        int j = e * DOUT * R + o * R + rr;
        s += mask_at(m, j, mode) ? c[j] : 0.f;
    }
    return s;
}

// ============================================================================
// Kernel 1 (FUSED): first half of the grid computes the masked coefficient
// sums g_sumw[o, r]; second half initializes g_fw with the DC + Nyquist
// terms, recomputing the two needed g_sumw rows (o=0, o=DOUT-1) directly
// from the inputs (80 cached values, broadcast) — no cross-kernel dep.
// ============================================================================
__global__ void k_prep(const float* __restrict__ c0, const float* __restrict__ c1,
                       const void* __restrict__ m0, const void* __restrict__ m1) {
    int idx = blockIdx.x * blockDim.x + threadIdx.x;
    const int total = DOUT * RTOT;
    const int mode = (g_viol[0] == 0u) ? 1 : ((g_viol[1] == 0u) ? 2 : 0);
    if (idx < total) {
        int o = idx / RTOT, r = idx % RTOT;
        float s = (r < R0) ? masked_sum(c0, m0, o, r, R0, mode)
                           : masked_sum(c1, m1, o, r - R0, R1, mode);
        g_sumw[o * RTOT + r] = s;
    } else if (idx < 2 * total) {
        int j = idx - total;
        int t = j / RTOT, r = j % RTOT;
        float s0, sN;
        if (r < R0) {
            s0 = masked_sum(c0, m0, 0, r, R0, mode);
            sN = masked_sum(c0, m0, DOUT - 1, r, R0, mode);
        } else {
            s0 = masked_sum(c1, m1, 0, r - R0, R1, mode);
            sN = masked_sum(c1, m1, DOUT - 1, r - R0, R1, mode);
        }
        const float inv = 0.015625f;                   // 1/sqrt(4096)
        float sgn = (t & 1) ? -inv : inv;
        g_fw[j] = s0 * inv + sN * sgn;
    }
}

// ============================================================================
// Kernel 2: frequency-parallel Fourier accumulation with rotation recurrence.
// grid (32, 16): blockIdx.x = t-tile of 128, blockIdx.y = 128-freq chunk.
// ============================================================================
__global__ void k_transform() {
    __shared__ float sc[128 * RTOT];       // 64 freqs (cos,sin rows) at a time
    int t = blockIdx.x * 128 + threadIdx.x;
    float acc[RTOT];
    #pragma unroll
    for (int r = 0; r < RTOT; ++r) acc[r] = 0.f;

    const float TWO_PI_OVER_N = 0.00153398078788564123f;
    float cd, sd;
    {
        int kt = t & 4095;
        int kt2 = (kt <= 2048) ? kt : (kt - 4096);
        __sincosf((float)kt2 * TWO_PI_OVER_N, &sd, &cd);
    }

    #pragma unroll
    for (int half = 0; half < 2; ++half) {
        int fs = 1 + blockIdx.y * 128 + half * 64;
        int nf = 2048 - fs; if (nf > 64) nf = 64;      // f max = 2047
        if (nf <= 0) break;
        int row0 = 2 * fs - 1;
        __syncthreads();
        for (int i = threadIdx.x; i < 2 * nf; i += 128) {
            const float4* src = (const float4*)(g_sumw + (size_t)(row0 + i) * RTOT);
            float4* dst = (float4*)(sc + i * RTOT);
            #pragma unroll
            for (int q = 0; q < 10; ++q) dst[q] = src[q];
        }
        __syncthreads();

        float cv, sv;
        {
            int k = (fs * t) & 4095;
            int k2 = (k <= 2048) ? k : (k - 4096);
            __sincosf((float)k2 * TWO_PI_OVER_N, &sv, &cv);
        }

        for (int j = 0; j < nf; ++j) {
            const float4* cc = (const float4*)(sc + (2 * j) * RTOT);
            const float4* ss = (const float4*)(sc + (2 * j + 1) * RTOT);
            #pragma unroll
            for (int q = 0; q < 10; ++q) {
                float4 a = cc[q]; float4 b = ss[q];
                acc[4*q+0] += a.x * cv + b.x * sv;
                acc[4*q+1] += a.y * cv + b.y * sv;
                acc[4*q+2] += a.z * cv + b.z * sv;
                acc[4*q+3] += a.w * cv + b.w * sv;
            }
            float ncv = cv * cd - sv * sd;
            sv = sv * cd + cv * sd;
            cv = ncv;
        }
    }
    const float s2 = 0.02209708691207961102f;          // sqrt(2/4096)
    float* dst = g_fw + (size_t)t * RTOT;
    #pragma unroll
    for (int r = 0; r < RTOT; ++r) atomicAdd(dst + r, acc[r] * s2);
}

// ============================================================================
// Kernel 3: W_eff = W_base + 0.5*(FW@enc); store fp16.
// ============================================================================
__global__ void k_build_w(const float* __restrict__ Wb,
                          const float* __restrict__ enc0,
                          const float* __restrict__ enc1) {
    __shared__ float fws[64 * RTOT];
    int d  = blockIdx.x * 128 + threadIdx.x;
    int o0 = blockIdx.y * 64;
    for (int i = threadIdx.x; i < 64 * RTOT / 4; i += 128)
        ((float4*)fws)[i] = ((const float4*)(g_fw + (size_t)o0 * RTOT))[i];
    float e[RTOT];
    #pragma unroll
    for (int r = 0; r < R0; ++r) e[r] = enc0[(size_t)r * DIN + d];
    #pragma unroll
    for (int r = 0; r < R1; ++r) e[R0 + r] = enc1[(size_t)r * DIN + d];
    __syncthreads();
    for (int oo = 0; oo < 64; ++oo) {
        size_t o = (size_t)(o0 + oo);
        float s = 0.f;
        const float4* fr = (const float4*)(fws + oo * RTOT);
        #pragma unroll
        for (int q = 0; q < 10; ++q) {
            float4 fv = fr[q];
            s += fv.x * e[4*q] + fv.y * e[4*q+1] + fv.z * e[4*q+2] + fv.w * e[4*q+3];
        }
        float v = Wb[o * DIN + d] + SCALING * s;
        g_wh[o * DIN + d] = __float2half_rn(v);
    }
}

// ============================================================================
// Kernel 4: convert x to fp16.
// ============================================================================
__global__ void k_cvt_x(const float* __restrict__ x) {
    size_t idx = (size_t)blockIdx.x * blockDim.x + threadIdx.x;  // over MROWS*DIN/4
    float4 v = ((const float4*)x)[idx];
    __half2 h01 = __floats2half2_rn(v.x, v.y);
    __half2 h23 = __floats2half2_rn(v.z, v.w);
    ((__half2*)g_xh)[2*idx]   = h01;
    ((__half2*)g_xh)[2*idx+1] = h23;
}

// ============================================================================
// Kernel 5: GEMM (R12 config — best: 128x128 CTA tile, 8 warps 64x32, 3-stage
// ring, one barrier per iter, spread cp.async issue, 2 CTAs/SM). UNCHANGED.
// ============================================================================
#define BM 128
#define BN 128
#define BK 64
#define STAGE_BYTES 32768   // A 16KB + B 16KB
#define NSTAGE 3
#define GEMM_SMEM   (STAGE_BYTES * NSTAGE)   // 98304
#define ITERS 64            // 4096 / 64

__global__ __launch_bounds__(256, 2) void k_gemm(const float* __restrict__ bias,
                                                 float* __restrict__ out) {
    extern __shared__ __align__(1024) unsigned char dynsmem[];
    const uint32_t smem_base = smem_u32(dynsmem);

    const int tid = threadIdx.x;
    const int wid = tid >> 5;
    const int lane = tid & 31;
    const int wm = wid & 1;          // 2 warps along M
    const int wn = wid >> 1;         // 4 warps along N
    const int m0 = blockIdx.y * BM;  // gridDim.y = 64
    const int n0 = blockIdx.x * BN;  // gridDim.x = 32

    const int ld_row = tid >> 3;          // 0..31 (+32*i)
    const int ld_c   = tid & 7;           // 16B column within 128B row

    float acc[4][4][4];                   // [mi][ni][reg]
    #pragma unroll
    for (int mi = 0; mi < 4; ++mi)
        #pragma unroll
        for (int ni = 0; ni < 4; ++ni)
            #pragma unroll
            for (int j = 0; j < 4; ++j) acc[mi][ni][j] = 0.f;

    const int a_row_l = (lane & 15);
    const int a_col_l = (lane & 16) ? 16 : 0;
    const int b_row_l = (lane & 7) + ((lane & 16) ? 8 : 0);
    const int b_col_l = (lane & 8) ? 16 : 0;

    const __half* Ap0 = g_xh + (size_t)m0 * DIN;
    const __half* Bp0 = g_wh + (size_t)n0 * DIN;

    auto issue_part = [&](int it, int slot, int part) {
        const int kc = it << 6;
        const int row = ld_row + part * 32;
        const uint32_t off = SMEM_SWIZZLE_128B((uint32_t)(row * 128 + ld_c * 16));
        const uint32_t sAb = smem_base + (uint32_t)slot * STAGE_BYTES;
        cp_async16(sAb + off,         Ap0 + kc + (size_t)row * DIN + ld_c * 8);
        cp_async16(sAb + 16384 + off, Bp0 + kc + (size_t)row * DIN + ld_c * 8);
    };
    auto issue_full = [&](int it, int slot) {
        #pragma unroll
        for (int p = 0; p < 4; ++p) issue_part(it, slot, p);
        cp_commit();
    };

    issue_full(0, 0);
    issue_full(1, 1);

    int slot = 0;        // slot of iter 'it'
    for (int it = 0; it < ITERS; ++it) {
        if (it + 1 < ITERS) cp_wait<1>();   // oldest (stage it) complete
        else                cp_wait<0>();
        __syncthreads();                    // compute(it-1) done; its slot is free

        const bool do_issue = (it + 2 < ITERS);
        int ns = slot + 2; if (ns >= NSTAGE) ns -= NSTAGE;

        const uint32_t sAb = smem_base + (uint32_t)slot * STAGE_BYTES;
        const uint32_t sBb = sAb + 16384;

        #pragma unroll
        for (int ks = 0; ks < 4; ++ks) {
            if (do_issue) issue_part(it + 2, ns, ks);   // spread STS across ks
            uint32_t a[4][4];
            uint32_t b[2][4];
            #pragma unroll
            for (int mi = 0; mi < 4; ++mi) {
                const int row = wm * 64 + mi * 16 + a_row_l;
                const int col = ks * 32 + a_col_l;
                const uint32_t addr = sAb + SMEM_SWIZZLE_128B((uint32_t)(row * 128 + col));
                ldm_x4(a[mi][0], a[mi][1], a[mi][2], a[mi][3], addr);
            }
            #pragma unroll
            for (int np = 0; np < 2; ++np) {
                const int row = wn * 32 + np * 16 + b_row_l;
                const int col = ks * 32 + b_col_l;
                const uint32_t addr = sBb + SMEM_SWIZZLE_128B((uint32_t)(row * 128 + col));
                ldm_x4(b[np][0], b[np][1], b[np][2], b[np][3], addr);
            }
            #pragma unroll
            for (int mi = 0; mi < 4; ++mi)
                #pragma unroll
                for (int ni = 0; ni < 4; ++ni) {
                    const uint32_t b0 = b[ni >> 1][(ni & 1) * 2];
                    const uint32_t b1 = b[ni >> 1][(ni & 1) * 2 + 1];
                    mma_f16(acc[mi][ni][0], acc[mi][ni][1], acc[mi][ni][2], acc[mi][ni][3],
                            a[mi][0], a[mi][1], a[mi][2], a[mi][3], b0, b1);
                }
        }
        if (do_issue) cp_commit();
        if (++slot >= NSTAGE) slot = 0;
    }

    // Epilogue: direct stores, float2 per fragment row, +bias.
    #pragma unroll
    for (int ni = 0; ni < 4; ++ni) {
        const int n = n0 + wn * 32 + ni * 8 + (lane & 3) * 2;
        const float bv0 = bias[n];
        const float bv1 = bias[n + 1];
        #pragma unroll
        for (int mi = 0; mi < 4; ++mi) {
            const int m = m0 + wm * 64 + mi * 16 + (lane >> 2);
            float2 v0 = make_float2(acc[mi][ni][0] + bv0, acc[mi][ni][1] + bv1);
            float2 v1 = make_float2(acc[mi][ni][2] + bv0, acc[mi][ni][3] + bv1);
            *(float2*)(out + (size_t)m * DOUT + n)       = v0;
            *(float2*)(out + (size_t)(m + 8) * DOUT + n) = v1;
        }
    }
}

// ============================================================================
// launch — single stream, 6 nodes (was 9 + 2 event nodes).
// ============================================================================
extern "C" void kernel_launch(void* const* d_in, const int* in_sizes, int n_in,
                              void* d_out, int out_size) {
    const float* x      = (const float*)d_in[0];
    const float* W_base = (const float*)d_in[1];
    const float* b_base = (const float*)d_in[2];
    const float* enc0   = (const float*)d_in[3];
    const float* enc1   = (const float*)d_in[4];
    const float* coefs0 = (const float*)d_in[5];
    const float* coefs1 = (const float*)d_in[6];
    const void*  mask0  = d_in[7];
    const void*  mask1  = d_in[8];
    float* out = (float*)d_out;

    static int smem_set = 0;
    if (!smem_set) {
        cudaFuncSetAttribute(k_gemm, cudaFuncAttributeMaxDynamicSharedMemorySize, GEMM_SMEM);
        smem_set = 1;
    }

    // 0) detect mask dtype (g_viol statically zeroed; ORs are idempotent)
    k_detect<<<(NEXP * DOUT * R0 / 4) / 256, 256>>>((const unsigned int*)mask0);
    // 1) fused: masked coefficient sums + DC/Nyquist init of g_fw
    k_prep<<<(2 * DOUT * RTOT + 255) / 256, 256>>>(coefs0, coefs1, mask0, mask1);
    // 2) Fourier transform of the 40 coefficient columns along O
    k_transform<<<dim3(32, 16), 128>>>();
    // 3) fold rank-40 update into effective weight (fp16)
    k_build_w<<<dim3(32, 64), 128>>>(W_base, enc0, enc1);
    // 4) convert activations to fp16
    k_cvt_x<<<(MROWS * DIN / 4) / 256, 256>>>(x);
    // 5) single-pass fp16 GEMM (R12 config)
    k_gemm<<<dim3(32, 64), 256, GEMM_SMEM>>>(b_base, out);
}